// round 7
// baseline (speedup 1.0000x reference)
#include <cuda_runtime.h>
#include <cuda_bf16.h>
#include <math.h>
#include <stdint.h>

#define BB 16
#define CIN 128
#define COUT 128
#define HH 64
#define WW 64
#define ATT 16
#define KN 4
#define BN_EPS 1e-5f

// ---------------------------------------------------------------------------
// scratch (device globals; no allocation allowed)
// ---------------------------------------------------------------------------
__device__ float g_pooled[BB * CIN];
__device__ float g_coef[BB * KN * 9];
__device__ float g_ch[BB * CIN];
__device__ float g_fl[BB * COUT];
__device__ float g_spa[BB * 9];
// agg filters pre-split to bf16: layout [b][tap][o(128)][i(128)]
__device__ __align__(128) __nv_bfloat16 g_ah[(size_t)BB * 9 * 128 * 128];
__device__ __align__(128) __nv_bfloat16 g_al[(size_t)BB * 9 * 128 * 128];
// x pre-split to bf16 NHWC: [b][y][x][i]
__device__ __align__(128) __nv_bfloat16 g_xh[(size_t)BB * HH * WW * CIN];
__device__ __align__(128) __nv_bfloat16 g_xl[(size_t)BB * HH * WW * CIN];

// ---------------------------------------------------------------------------
// mma helper
// ---------------------------------------------------------------------------
__device__ __forceinline__ void mma16816(float* c, const uint32_t* a, const uint32_t* b) {
    asm volatile(
        "mma.sync.aligned.m16n8k16.row.col.f32.bf16.bf16.f32 "
        "{%0,%1,%2,%3}, {%4,%5,%6,%7}, {%8,%9}, {%0,%1,%2,%3};"
        : "+f"(c[0]), "+f"(c[1]), "+f"(c[2]), "+f"(c[3])
        : "r"(a[0]), "r"(a[1]), "r"(a[2]), "r"(a[3]), "r"(b[0]), "r"(b[1]));
}

// ---------------- kernel 1: global average pool ----------------------------
__global__ void pool_kernel(const float* __restrict__ x) {
    int bi = blockIdx.x;
    const float4* xp = (const float4*)(x + (size_t)bi * HH * WW);
    float s = 0.f;
    for (int t = threadIdx.x; t < HH * WW / 4; t += 256) {
        float4 v = xp[t];
        s += v.x + v.y + v.z + v.w;
    }
#pragma unroll
    for (int o = 16; o; o >>= 1) s += __shfl_down_sync(0xffffffff, s, o);
    __shared__ float ws[8];
    if ((threadIdx.x & 31) == 0) ws[threadIdx.x >> 5] = s;
    __syncthreads();
    if (threadIdx.x == 0) {
        float t = 0.f;
#pragma unroll
        for (int k = 0; k < 8; k++) t += ws[k];
        g_pooled[bi] = t * (1.0f / (HH * WW));
    }
}

// ---------------- kernel 1b: x -> NHWC bf16 hi/lo split (R4 verbatim) ------
__global__ void __launch_bounds__(256) xsplit_kernel(const float* __restrict__ x) {
    __shared__ float tile[128][66];
    const int y = blockIdx.x;
    const int b = blockIdx.y;
    const float* xp = x + ((size_t)b * CIN * HH + y) * WW;
#pragma unroll
    for (int it = 0; it < 16; it++) {
        int i = it * 8 + (threadIdx.x >> 5);
        int gx = (threadIdx.x & 31) * 2;
        float2 v = *(const float2*)(xp + (size_t)i * HH * WW + gx);
        tile[i][gx] = v.x;
        tile[i][gx + 1] = v.y;
    }
    __syncthreads();
    const int gx = threadIdx.x >> 2;
    const int part = threadIdx.x & 3;
    __nv_bfloat16 hi[32], lo[32];
#pragma unroll
    for (int ii = 0; ii < 32; ii++) {
        float v = tile[part * 32 + ii][gx];
        __nv_bfloat16 h = __float2bfloat16(v);
        hi[ii] = h;
        lo[ii] = __float2bfloat16(v - __bfloat162float(h));
    }
    size_t base = (((size_t)b * HH + y) * WW + gx) * CIN + part * 32;
#pragma unroll
    for (int j = 0; j < 4; j++) {
        *(uint4*)(g_xh + base + j * 8) = ((const uint4*)hi)[j];
        *(uint4*)(g_xl + base + j * 8) = ((const uint4*)lo)[j];
    }
}

// ---------------- kernel 2: attention trunk + branches (1 block) -----------
__global__ void attn_kernel(
    const float* __restrict__ fc_w,
    const float* __restrict__ bn_gamma, const float* __restrict__ bn_beta,
    const float* __restrict__ bn_mean, const float* __restrict__ bn_var,
    const float* __restrict__ ch_w, const float* __restrict__ ch_b,
    const float* __restrict__ flt_w, const float* __restrict__ flt_b,
    const float* __restrict__ spa_w, const float* __restrict__ spa_b,
    const float* __restrict__ fld_w, const float* __restrict__ fld_b,
    const float* __restrict__ ker_w, const float* __restrict__ ker_b) {
    __shared__ float sp[BB][CIN];
    __shared__ float sh[BB][ATT];
    __shared__ float sfld[BB][9];
    __shared__ float sker[BB][KN];
    int tid = threadIdx.x;
    for (int t = tid; t < BB * CIN; t += 256) sp[t / CIN][t % CIN] = g_pooled[t];
    __syncthreads();
    {
        int b = tid / ATT, a = tid % ATT;
        float s = 0.f;
#pragma unroll 16
        for (int i = 0; i < CIN; i++) s += sp[b][i] * fc_w[a * CIN + i];
        float inv = rsqrtf(bn_var[a] + BN_EPS);
        s = (s - bn_mean[a]) * (bn_gamma[a] * inv) + bn_beta[a];
        sh[b][a] = fmaxf(s, 0.f);
    }
    __syncthreads();
    for (int t = tid; t < BB * CIN; t += 256) {
        int b = t / CIN, i = t % CIN;
        float s = ch_b[i];
#pragma unroll
        for (int a = 0; a < ATT; a++) s += sh[b][a] * ch_w[i * ATT + a];
        g_ch[t] = 1.f / (1.f + expf(-s));
    }
    for (int t = tid; t < BB * COUT; t += 256) {
        int b = t / COUT, o = t % COUT;
        float s = flt_b[o];
#pragma unroll
        for (int a = 0; a < ATT; a++) s += sh[b][a] * flt_w[o * ATT + a];
        g_fl[t] = 1.f / (1.f + expf(-s));
    }
    for (int t = tid; t < BB * 9; t += 256) {
        int b = t / 9, j = t % 9;
        float s = spa_b[j];
#pragma unroll
        for (int a = 0; a < ATT; a++) s += sh[b][a] * spa_w[j * ATT + a];
        g_spa[t] = 1.f / (1.f + expf(-s));
        float s2 = fld_b[j];
#pragma unroll
        for (int a = 0; a < ATT; a++) s2 += sh[b][a] * fld_w[j * ATT + a];
        sfld[b][j] = 1.f / (1.f + expf(-s2));
    }
    if (tid < BB * KN) {
        int b = tid / KN, n = tid % KN;
        float s = ker_b[n];
#pragma unroll
        for (int a = 0; a < ATT; a++) s += sh[b][a] * ker_w[n * ATT + a];
        sker[b][n] = s;
    }
    __syncthreads();
    if (tid < BB) {
        int b = tid;
        float m = -1e30f;
#pragma unroll
        for (int n = 0; n < KN; n++) m = fmaxf(m, sker[b][n]);
        float e[KN], sum = 0.f;
#pragma unroll
        for (int n = 0; n < KN; n++) { e[n] = expf(sker[b][n] - m); sum += e[n]; }
#pragma unroll
        for (int n = 0; n < KN; n++) sker[b][n] = e[n] / sum;
    }
    __syncthreads();
    for (int t = tid; t < BB * KN * 9; t += 256) {
        int b = t / (KN * 9), n = (t / 9) % KN, j = t % 9;
        g_coef[t] = sker[b][n] * sfld[b][j];
    }
}

// ---------------- kernel 3: aggregation -> bf16 hi/lo filter tiles ---------
// grid (64, 3): blockIdx.y owns pq-triple {3y, 3y+1, 3y+2}. Weight read ONCE.
// thread <-> (o,i); batch loop in groups of 4 (acc[4], ~70 regs).
__global__ void __launch_bounds__(256) agg_kernel(const float* __restrict__ weight) {
    __shared__ float scoef[BB * KN * 9];
    __shared__ float sch[BB * CIN];
    __shared__ float sfl[BB * COUT];
    __shared__ float sspa[BB * 9];
    for (int t = threadIdx.x; t < BB * KN * 9; t += 256) scoef[t] = g_coef[t];
    for (int t = threadIdx.x; t < BB * CIN; t += 256) sch[t] = g_ch[t];
    for (int t = threadIdx.x; t < BB * COUT; t += 256) sfl[t] = g_fl[t];
    for (int t = threadIdx.x; t < BB * 9; t += 256) sspa[t] = g_spa[t];
    __syncthreads();
    const int oi = blockIdx.x * 256 + threadIdx.x;   // 0..16383
    const int o = oi >> 7, i = oi & 127;
    const int pq0 = blockIdx.y * 3;
    const size_t nstride = (size_t)COUT * CIN * 81;
    const float* wbase = weight + (size_t)oi * 81;
#pragma unroll 1
    for (int dpq = 0; dpq < 3; dpq++) {
        const int pq = pq0 + dpq;
        float w[KN * 9];
#pragma unroll
        for (int n = 0; n < KN; n++)
#pragma unroll
            for (int uv = 0; uv < 9; uv++)
                w[n * 9 + uv] = __ldg(wbase + n * nstride + pq * 9 + uv);
        const float sp = sspa[0 * 9 + pq];  // placeholder to keep compiler calm
        (void)sp;
#pragma unroll 1
        for (int bg = 0; bg < 4; bg++) {
            const int b0 = bg * 4;
            float acc[4] = {0.f, 0.f, 0.f, 0.f};
#pragma unroll
            for (int k = 0; k < KN * 9; k++) {
                float wv = w[k];
#pragma unroll
                for (int bb = 0; bb < 4; bb++)
                    acc[bb] += wv * scoef[(b0 + bb) * (KN * 9) + k];
            }
#pragma unroll
            for (int bb = 0; bb < 4; bb++) {
                int b = b0 + bb;
                float s = acc[bb] * sch[b * CIN + i] * sfl[b * COUT + o] * sspa[b * 9 + pq];
                __nv_bfloat16 h = __float2bfloat16(s);
                __nv_bfloat16 l = __float2bfloat16(s - __bfloat162float(h));
                size_t oidx = (((size_t)b * 9 + pq) * 128 + o) * 128 + i;
                g_ah[oidx] = h;
                g_al[oidx] = l;
            }
        }
    }
}

// ---------------- kernel 4: implicit-GEMM conv on mma.sync (bf16 hi/lo) ----
// R6 conv with ONE change: B tiles copied from pre-split NHWC g_xh/g_xl
// (4x LDG.128 per thread) instead of 16 scalar LDG + cvt chain.
#define APITCH 80   // 32 k * 2B = 64B payload, padded to 80B (conflict-free)

__global__ void __launch_bounds__(256, 2) conv_mma_kernel(float* __restrict__ out) {
    __shared__ __align__(16) char sm[4 * 128 * APITCH];
    char* smAh = sm;
    char* smAl = sm + 128 * APITCH;
    char* smBh = sm + 2 * 128 * APITCH;
    char* smBl = sm + 3 * 128 * APITCH;

    const int tid = threadIdx.x;
    const int wid = tid >> 5;
    const int lid = tid & 31;
    const int b = blockIdx.y;
    const int y0 = blockIdx.x * 2;         // two output rows y0, y0+1

    const int wm = wid >> 2;               // 0..1 -> m base 0/64
    const int wn = wid & 3;                // 0..3 -> n base 0/32/64/96
    const int mbase = wm * 64;
    const int nbase = wn * 32;

    float acc[4][4][4];
#pragma unroll
    for (int mt = 0; mt < 4; mt++)
#pragma unroll
        for (int nt = 0; nt < 4; nt++)
#pragma unroll
            for (int r = 0; r < 4; r++) acc[mt][nt][r] = 0.f;

    // B-build thread mapping: n = tid & 127 (px index), ihalf = tid >> 7
    const int bn = tid & 127;
    const int ihalf = tid >> 7;            // 0/1 -> i offset 0/16 within chunk
    const int brp = bn >> 6;               // row select
    const int bpx = bn & 63;

    // A-copy thread mapping: o = tid >> 1, u = tid & 1 (2 x uint4 each)
    const int ao = tid >> 1;
    const int au = tid & 1;

    for (int tap = 0; tap < 9; tap++) {
        const int p = tap / 3 - 1;
        const int q = tap % 3 - 1;
        const int gy = y0 + brp + p;
        const int gx = bpx + q;
        const bool inb = (gx >= 0) && (gx < WW) && (gy >= 0) && (gy < HH);
        const size_t xoff =
            (((size_t)b * HH + (inb ? gy : 0)) * WW + (inb ? gx : 0)) * CIN + ihalf * 16;
        const size_t abase = (((size_t)b * 9 + tap) * 128 + ao) * 128;

        for (int kc = 0; kc < 4; kc++) {
            const int ic0 = kc * 32;
            // ---- A copy: 128 o x 32 k bf16 hi/lo ----
            {
                const uint4* rh = (const uint4*)(g_ah + abase + ic0);
                const uint4* rl = (const uint4*)(g_al + abase + ic0);
                uint4 h0 = rh[au * 2], h1 = rh[au * 2 + 1];
                uint4 l0 = rl[au * 2], l1 = rl[au * 2 + 1];
                char* dh = smAh + ao * APITCH + au * 32;
                char* dl = smAl + ao * APITCH + au * 32;
                *(uint4*)(dh) = h0;  *(uint4*)(dh + 16) = h1;
                *(uint4*)(dl) = l0;  *(uint4*)(dl + 16) = l1;
            }
            // ---- B copy: [n=128][k=32] from pre-split NHWC (4x LDG.128) ----
            {
                uint4 h0, h1, l0, l1;
                if (inb) {
                    const uint4* ph = (const uint4*)(g_xh + xoff + ic0);
                    const uint4* pl = (const uint4*)(g_xl + xoff + ic0);
                    h0 = ph[0]; h1 = ph[1];
                    l0 = pl[0]; l1 = pl[1];
                } else {
                    h0 = h1 = l0 = l1 = make_uint4(0, 0, 0, 0);
                }
                char* dh = smBh + bn * APITCH + ihalf * 32;
                char* dl = smBl + bn * APITCH + ihalf * 32;
                *(uint4*)(dh) = h0;  *(uint4*)(dh + 16) = h1;
                *(uint4*)(dl) = l0;  *(uint4*)(dl + 16) = l1;
            }
            __syncthreads();

            // ---- MMA: 3 passes (AhBh, AlBh, AhBl) x 2 k16 steps ----
            const int arow = lid >> 2;             // 0..7
            const int akb = (lid & 3) * 4;         // k byte offset base
#pragma unroll
            for (int pass = 0; pass < 3; pass++) {
                const char* As = (pass == 1) ? smAl : smAh;
                const char* Bs = (pass == 2) ? smBl : smBh;
#pragma unroll
                for (int ks = 0; ks < 2; ks++) {
                    const int kbyte = akb + ks * 32;
                    uint32_t bf[4][2];
#pragma unroll
                    for (int nt = 0; nt < 4; nt++) {
                        const char* bp = Bs + (nbase + nt * 8 + arow) * APITCH + kbyte;
                        bf[nt][0] = *(const uint32_t*)(bp);
                        bf[nt][1] = *(const uint32_t*)(bp + 16);
                    }
#pragma unroll
                    for (int mt = 0; mt < 4; mt++) {
                        uint32_t af[4];
                        const char* ap = As + (mbase + mt * 16 + arow) * APITCH + kbyte;
                        af[0] = *(const uint32_t*)(ap);
                        af[1] = *(const uint32_t*)(ap + 8 * APITCH);
                        af[2] = *(const uint32_t*)(ap + 16);
                        af[3] = *(const uint32_t*)(ap + 8 * APITCH + 16);
#pragma unroll
                        for (int nt = 0; nt < 4; nt++)
                            mma16816(acc[mt][nt], af, bf[nt]);
                    }
                }
            }
            __syncthreads();
        }
    }

    // ---- epilogue: direct stores (fl already folded into agg) ----
    float* ob = out + (size_t)b * COUT * HH * WW;
#pragma unroll
    for (int mt = 0; mt < 4; mt++) {
        const int o = mbase + mt * 16 + (lid >> 2);
#pragma unroll
        for (int nt = 0; nt < 4; nt++) {
            const int nn = nbase + nt * 8 + (lid & 3) * 2;
            const int rp = nn >> 6, px = nn & 63;
            float* dst = ob + ((size_t)o * HH + (y0 + rp)) * WW + px;
            float2 v0 = make_float2(acc[mt][nt][0], acc[mt][nt][1]);
            float2 v1 = make_float2(acc[mt][nt][2], acc[mt][nt][3]);
            *(float2*)(dst) = v0;
            *(float2*)(dst + 8 * (size_t)HH * WW) = v1;
        }
    }
}

// ---------------- launch ----------------------------------------------------
extern "C" void kernel_launch(void* const* d_in, const int* in_sizes, int n_in,
                              void* d_out, int out_size) {
    const float* x        = (const float*)d_in[0];
    const float* weight   = (const float*)d_in[1];
    const float* fc_w     = (const float*)d_in[2];
    const float* bn_gamma = (const float*)d_in[3];
    const float* bn_beta  = (const float*)d_in[4];
    const float* bn_mean  = (const float*)d_in[5];
    const float* bn_var   = (const float*)d_in[6];
    const float* ch_w     = (const float*)d_in[7];
    const float* ch_b     = (const float*)d_in[8];
    const float* flt_w    = (const float*)d_in[9];
    const float* flt_b    = (const float*)d_in[10];
    const float* spa_w    = (const float*)d_in[11];
    const float* spa_b    = (const float*)d_in[12];
    const float* fld_w    = (const float*)d_in[13];
    const float* fld_b    = (const float*)d_in[14];
    const float* ker_w    = (const float*)d_in[15];
    const float* ker_b    = (const float*)d_in[16];
    float* out = (float*)d_out;

    pool_kernel<<<BB * CIN, 256>>>(x);
    xsplit_kernel<<<dim3(HH, BB), 256>>>(x);
    attn_kernel<<<1, 256>>>(fc_w, bn_gamma, bn_beta, bn_mean, bn_var,
                            ch_w, ch_b, flt_w, flt_b, spa_w, spa_b,
                            fld_w, fld_b, ker_w, ker_b);
    agg_kernel<<<dim3(64, 3), 256>>>(weight);
    conv_mma_kernel<<<dim3(32, BB), 256>>>(out);
}

// round 8
// speedup vs baseline: 1.2276x; 1.2276x over previous
#include <cuda_runtime.h>
#include <cuda_bf16.h>
#include <math.h>
#include <stdint.h>

#define BB 16
#define CIN 128
#define COUT 128
#define HH 64
#define WW 64
#define ATT 16
#define KN 4
#define BN_EPS 1e-5f

// ---------------------------------------------------------------------------
// scratch (device globals; no allocation allowed)
// ---------------------------------------------------------------------------
__device__ float g_pooled[BB * CIN];
__device__ float g_coef[BB * KN * 9];
__device__ float g_ch[BB * CIN];
__device__ float g_fl[BB * COUT];
__device__ float g_spa[BB * 9];
// agg filters pre-split to bf16: layout [b][tap][o(128)][i(128)]
__device__ __align__(128) __nv_bfloat16 g_ah[(size_t)BB * 9 * 128 * 128];
__device__ __align__(128) __nv_bfloat16 g_al[(size_t)BB * 9 * 128 * 128];

// ---------------------------------------------------------------------------
// asm helpers
// ---------------------------------------------------------------------------
__device__ __forceinline__ uint32_t smem_u32(const void* p) {
    uint32_t a;
    asm("{ .reg .u64 t; cvta.to.shared.u64 t, %1; cvt.u32.u64 %0, t; }" : "=r"(a) : "l"(p));
    return a;
}
__device__ __forceinline__ void ldsm_x4(uint32_t* r, uint32_t a) {
    asm volatile("ldmatrix.sync.aligned.m8n8.x4.shared.b16 {%0,%1,%2,%3}, [%4];"
                 : "=r"(r[0]), "=r"(r[1]), "=r"(r[2]), "=r"(r[3]) : "r"(a));
}
__device__ __forceinline__ void ldsm_x2(uint32_t* r, uint32_t a) {
    asm volatile("ldmatrix.sync.aligned.m8n8.x2.shared.b16 {%0,%1}, [%2];"
                 : "=r"(r[0]), "=r"(r[1]) : "r"(a));
}
__device__ __forceinline__ void mma16816(float* c, const uint32_t* a, const uint32_t* b) {
    asm volatile(
        "mma.sync.aligned.m16n8k16.row.col.f32.bf16.bf16.f32 "
        "{%0,%1,%2,%3}, {%4,%5,%6,%7}, {%8,%9}, {%0,%1,%2,%3};"
        : "+f"(c[0]), "+f"(c[1]), "+f"(c[2]), "+f"(c[3])
        : "r"(a[0]), "r"(a[1]), "r"(a[2]), "r"(a[3]), "r"(b[0]), "r"(b[1]));
}

// ---------------- kernel 1: global average pool ----------------------------
__global__ void pool_kernel(const float* __restrict__ x) {
    int bi = blockIdx.x;
    const float4* xp = (const float4*)(x + (size_t)bi * HH * WW);
    float s = 0.f;
    for (int t = threadIdx.x; t < HH * WW / 4; t += 256) {
        float4 v = xp[t];
        s += v.x + v.y + v.z + v.w;
    }
#pragma unroll
    for (int o = 16; o; o >>= 1) s += __shfl_down_sync(0xffffffff, s, o);
    __shared__ float ws[8];
    if ((threadIdx.x & 31) == 0) ws[threadIdx.x >> 5] = s;
    __syncthreads();
    if (threadIdx.x == 0) {
        float t = 0.f;
#pragma unroll
        for (int k = 0; k < 8; k++) t += ws[k];
        g_pooled[bi] = t * (1.0f / (HH * WW));
    }
}

// ---------------- kernel 2: attention trunk + branches (1 block) -----------
__global__ void attn_kernel(
    const float* __restrict__ fc_w,
    const float* __restrict__ bn_gamma, const float* __restrict__ bn_beta,
    const float* __restrict__ bn_mean, const float* __restrict__ bn_var,
    const float* __restrict__ ch_w, const float* __restrict__ ch_b,
    const float* __restrict__ flt_w, const float* __restrict__ flt_b,
    const float* __restrict__ spa_w, const float* __restrict__ spa_b,
    const float* __restrict__ fld_w, const float* __restrict__ fld_b,
    const float* __restrict__ ker_w, const float* __restrict__ ker_b) {
    __shared__ float sp[BB][CIN];
    __shared__ float sh[BB][ATT];
    __shared__ float sfld[BB][9];
    __shared__ float sker[BB][KN];
    int tid = threadIdx.x;
    for (int t = tid; t < BB * CIN; t += 256) sp[t / CIN][t % CIN] = g_pooled[t];
    __syncthreads();
    {
        int b = tid / ATT, a = tid % ATT;
        float s = 0.f;
#pragma unroll 16
        for (int i = 0; i < CIN; i++) s += sp[b][i] * fc_w[a * CIN + i];
        float inv = rsqrtf(bn_var[a] + BN_EPS);
        s = (s - bn_mean[a]) * (bn_gamma[a] * inv) + bn_beta[a];
        sh[b][a] = fmaxf(s, 0.f);
    }
    __syncthreads();
    for (int t = tid; t < BB * CIN; t += 256) {
        int b = t / CIN, i = t % CIN;
        float s = ch_b[i];
#pragma unroll
        for (int a = 0; a < ATT; a++) s += sh[b][a] * ch_w[i * ATT + a];
        g_ch[t] = 1.f / (1.f + expf(-s));
    }
    for (int t = tid; t < BB * COUT; t += 256) {
        int b = t / COUT, o = t % COUT;
        float s = flt_b[o];
#pragma unroll
        for (int a = 0; a < ATT; a++) s += sh[b][a] * flt_w[o * ATT + a];
        g_fl[t] = 1.f / (1.f + expf(-s));
    }
    for (int t = tid; t < BB * 9; t += 256) {
        int b = t / 9, j = t % 9;
        float s = spa_b[j];
#pragma unroll
        for (int a = 0; a < ATT; a++) s += sh[b][a] * spa_w[j * ATT + a];
        g_spa[t] = 1.f / (1.f + expf(-s));
        float s2 = fld_b[j];
#pragma unroll
        for (int a = 0; a < ATT; a++) s2 += sh[b][a] * fld_w[j * ATT + a];
        sfld[b][j] = 1.f / (1.f + expf(-s2));
    }
    if (tid < BB * KN) {
        int b = tid / KN, n = tid % KN;
        float s = ker_b[n];
#pragma unroll
        for (int a = 0; a < ATT; a++) s += sh[b][a] * ker_w[n * ATT + a];
        sker[b][n] = s;
    }
    __syncthreads();
    if (tid < BB) {
        int b = tid;
        float m = -1e30f;
#pragma unroll
        for (int n = 0; n < KN; n++) m = fmaxf(m, sker[b][n]);
        float e[KN], sum = 0.f;
#pragma unroll
        for (int n = 0; n < KN; n++) { e[n] = expf(sker[b][n] - m); sum += e[n]; }
#pragma unroll
        for (int n = 0; n < KN; n++) sker[b][n] = e[n] / sum;
    }
    __syncthreads();
    for (int t = tid; t < BB * KN * 9; t += 256) {
        int b = t / (KN * 9), n = (t / 9) % KN, j = t % 9;
        g_coef[t] = sker[b][n] * sfld[b][j];
    }
}

// ---------------- kernel 3: aggregation -> bf16 hi/lo filter tiles ---------
// grid (64, 9): blockIdx.y owns ONE pq. Weight read exactly once, 576 blocks.
// thread <-> (o,i); batch loop in groups of 4 (acc[4], ~60 regs).
__global__ void __launch_bounds__(256) agg_kernel(const float* __restrict__ weight) {
    __shared__ float scoef[BB * KN * 9];
    __shared__ float sch[BB * CIN];
    __shared__ float sfl[BB * COUT];
    __shared__ float sspa[BB * 9];
    for (int t = threadIdx.x; t < BB * KN * 9; t += 256) scoef[t] = g_coef[t];
    for (int t = threadIdx.x; t < BB * CIN; t += 256) sch[t] = g_ch[t];
    for (int t = threadIdx.x; t < BB * COUT; t += 256) sfl[t] = g_fl[t];
    for (int t = threadIdx.x; t < BB * 9; t += 256) sspa[t] = g_spa[t];
    __syncthreads();
    const int oi = blockIdx.x * 256 + threadIdx.x;   // 0..16383
    const int o = oi >> 7, i = oi & 127;
    const int pq = blockIdx.y;
    const size_t nstride = (size_t)COUT * CIN * 81;
    const float* wbase = weight + (size_t)oi * 81 + pq * 9;
    float w[KN * 9];
#pragma unroll
    for (int n = 0; n < KN; n++)
#pragma unroll
        for (int uv = 0; uv < 9; uv++)
            w[n * 9 + uv] = __ldg(wbase + n * nstride + uv);
#pragma unroll 1
    for (int bg = 0; bg < 4; bg++) {
        const int b0 = bg * 4;
        float acc[4] = {0.f, 0.f, 0.f, 0.f};
#pragma unroll
        for (int k = 0; k < KN * 9; k++) {
            float wv = w[k];
#pragma unroll
            for (int bb = 0; bb < 4; bb++)
                acc[bb] += wv * scoef[(b0 + bb) * (KN * 9) + k];
        }
#pragma unroll
        for (int bb = 0; bb < 4; bb++) {
            int b = b0 + bb;
            float s = acc[bb] * sch[b * CIN + i] * sfl[b * COUT + o] * sspa[b * 9 + pq];
            __nv_bfloat16 h = __float2bfloat16(s);
            __nv_bfloat16 l = __float2bfloat16(s - __bfloat162float(h));
            size_t oidx = (((size_t)b * 9 + pq) * 128 + o) * 128 + i;
            g_ah[oidx] = h;
            g_al[oidx] = l;
        }
    }
}

// ---------------- kernel 4: implicit-GEMM conv on mma.sync (bf16 hi/lo) ----
// R6 conv (243.3us) with ONE change: MMA-phase fragment loads via ldmatrix
// (x4 for A, x2 for B) instead of 144 scalar LDS.32 per warp per chunk.
// Copy phase (coalesced NCHW B-build + A copy) byte-identical to R6.
#define APITCH 80   // 32 k * 2B = 64B payload, padded to 80B (conflict-free)

__global__ void __launch_bounds__(256, 2) conv_mma_kernel(const float* __restrict__ x,
                                                          float* __restrict__ out) {
    // smem: A_h | A_l | B_h | B_l, each 128 rows x APITCH bytes = 10240
    __shared__ __align__(16) char sm[4 * 128 * APITCH];
    char* smAh = sm;
    char* smAl = sm + 128 * APITCH;
    char* smBh = sm + 2 * 128 * APITCH;
    char* smBl = sm + 3 * 128 * APITCH;
    const uint32_t sbase = smem_u32(sm);

    const int tid = threadIdx.x;
    const int wid = tid >> 5;
    const int lid = tid & 31;
    const int b = blockIdx.y;
    const int y0 = blockIdx.x * 2;         // two output rows y0, y0+1

    const int wm = wid >> 2;               // 0..1 -> m base 0/64
    const int wn = wid & 3;                // 0..3 -> n base 0/32/64/96
    const int mbase = wm * 64;
    const int nbase = wn * 32;

    float acc[4][4][4];
#pragma unroll
    for (int mt = 0; mt < 4; mt++)
#pragma unroll
        for (int nt = 0; nt < 4; nt++)
#pragma unroll
            for (int r = 0; r < 4; r++) acc[mt][nt][r] = 0.f;

    const float* xb = x + (size_t)b * CIN * HH * WW;

    // B-build thread mapping: n = tid & 127 (px index), ihalf = tid >> 7
    const int bn = tid & 127;
    const int ihalf = tid >> 7;            // 0/1 -> i offset 0/16 within chunk
    const int brp = bn >> 6;               // row select
    const int bpx = bn & 63;

    // A-copy thread mapping: o = tid >> 1, u = tid & 1 (2 x uint4 each)
    const int ao = tid >> 1;
    const int au = tid & 1;

    // ldmatrix lane mapping (validated in R5): r8 rows, g1 row-half, g2 k-half
    const int r8 = lid & 7;
    const int g1 = (lid >> 3) & 1;
    const int g2 = lid >> 4;
    const uint32_t aoff = (uint32_t)((mbase + g1 * 8 + r8) * APITCH + g2 * 16);
    const uint32_t boff = (uint32_t)((nbase + r8) * APITCH + g1 * 16);

    for (int tap = 0; tap < 9; tap++) {
        const int p = tap / 3 - 1;
        const int q = tap % 3 - 1;
        const int gy = y0 + brp + p;
        const int gx = bpx + q;
        const bool inb = (gx >= 0) && (gx < WW) && (gy >= 0) && (gy < HH);
        const float* xpix = xb + ((size_t)gy * WW + gx);
        const size_t abase = (((size_t)b * 9 + tap) * 128 + ao) * 128;

        for (int kc = 0; kc < 4; kc++) {
            const int ic0 = kc * 32;
            // ---- A copy: 128 o x 32 k bf16 hi/lo ----
            {
                const uint4* rh = (const uint4*)(g_ah + abase + ic0);
                const uint4* rl = (const uint4*)(g_al + abase + ic0);
                uint4 h0 = rh[au * 2], h1 = rh[au * 2 + 1];
                uint4 l0 = rl[au * 2], l1 = rl[au * 2 + 1];
                char* dh = smAh + ao * APITCH + au * 32;
                char* dl = smAl + ao * APITCH + au * 32;
                *(uint4*)(dh) = h0;  *(uint4*)(dh + 16) = h1;
                *(uint4*)(dl) = l0;  *(uint4*)(dl + 16) = l1;
            }
            // ---- B build: [n=128][k=32] coalesced NCHW loads + cvt ----
            {
                __nv_bfloat16 hi[16], lo[16];
                const float* src = xpix + (size_t)(ic0 + ihalf * 16) * (HH * WW);
#pragma unroll
                for (int kk = 0; kk < 16; kk++) {
                    float v = inb ? __ldg(src + (size_t)kk * (HH * WW)) : 0.f;
                    __nv_bfloat16 h = __float2bfloat16(v);
                    hi[kk] = h;
                    lo[kk] = __float2bfloat16(v - __bfloat162float(h));
                }
                char* dh = smBh + bn * APITCH + ihalf * 32;
                char* dl = smBl + bn * APITCH + ihalf * 32;
                *(uint4*)(dh) = *(const uint4*)(hi);
                *(uint4*)(dh + 16) = *(const uint4*)(hi + 8);
                *(uint4*)(dl) = *(const uint4*)(lo);
                *(uint4*)(dl + 16) = *(const uint4*)(lo + 8);
            }
            __syncthreads();

            // ---- MMA: 3 passes (AhBh, AlBh, AhBl) x 2 k16, ldmatrix loads ----
#pragma unroll
            for (int pass = 0; pass < 3; pass++) {
                const uint32_t Asm = sbase + (pass == 1 ? 10240u : 0u);
                const uint32_t Bsm = sbase + 20480u + (pass == 2 ? 10240u : 0u);
#pragma unroll
                for (int ks = 0; ks < 2; ks++) {
                    const uint32_t kb = (uint32_t)(ks * 32);
                    uint32_t bfr[4][2];
#pragma unroll
                    for (int nt = 0; nt < 4; nt++)
                        ldsm_x2(bfr[nt], Bsm + boff + (uint32_t)(nt * 8 * APITCH) + kb);
#pragma unroll
                    for (int mt = 0; mt < 4; mt++) {
                        uint32_t afr[4];
                        ldsm_x4(afr, Asm + aoff + (uint32_t)(mt * 16 * APITCH) + kb);
#pragma unroll
                        for (int nt = 0; nt < 4; nt++)
                            mma16816(acc[mt][nt], afr, bfr[nt]);
                    }
                }
            }
            __syncthreads();
        }
    }

    // ---- epilogue: direct stores (fl already folded into agg) ----
    float* ob = out + (size_t)b * COUT * HH * WW;
#pragma unroll
    for (int mt = 0; mt < 4; mt++) {
        const int o = mbase + mt * 16 + (lid >> 2);
#pragma unroll
        for (int nt = 0; nt < 4; nt++) {
            const int nn = nbase + nt * 8 + (lid & 3) * 2;
            const int rp = nn >> 6, px = nn & 63;
            float* dst = ob + ((size_t)o * HH + (y0 + rp)) * WW + px;
            float2 v0 = make_float2(acc[mt][nt][0], acc[mt][nt][1]);
            float2 v1 = make_float2(acc[mt][nt][2], acc[mt][nt][3]);
            *(float2*)(dst) = v0;
            *(float2*)(dst + 8 * (size_t)HH * WW) = v1;
        }
    }
}

// ---------------- launch ----------------------------------------------------
extern "C" void kernel_launch(void* const* d_in, const int* in_sizes, int n_in,
                              void* d_out, int out_size) {
    const float* x        = (const float*)d_in[0];
    const float* weight   = (const float*)d_in[1];
    const float* fc_w     = (const float*)d_in[2];
    const float* bn_gamma = (const float*)d_in[3];
    const float* bn_beta  = (const float*)d_in[4];
    const float* bn_mean  = (const float*)d_in[5];
    const float* bn_var   = (const float*)d_in[6];
    const float* ch_w     = (const float*)d_in[7];
    const float* ch_b     = (const float*)d_in[8];
    const float* flt_w    = (const float*)d_in[9];
    const float* flt_b    = (const float*)d_in[10];
    const float* spa_w    = (const float*)d_in[11];
    const float* spa_b    = (const float*)d_in[12];
    const float* fld_w    = (const float*)d_in[13];
    const float* fld_b    = (const float*)d_in[14];
    const float* ker_w    = (const float*)d_in[15];
    const float* ker_b    = (const float*)d_in[16];
    float* out = (float*)d_out;

    pool_kernel<<<BB * CIN, 256>>>(x);
    attn_kernel<<<1, 256>>>(fc_w, bn_gamma, bn_beta, bn_mean, bn_var,
                            ch_w, ch_b, flt_w, flt_b, spa_w, spa_b,
                            fld_w, fld_b, ker_w, ker_b);
    agg_kernel<<<dim3(64, 9), 256>>>(weight);
    conv_mma_kernel<<<dim3(32, BB), 256>>>(x, out);
}